// round 16
// baseline (speedup 1.0000x reference)
#include <cuda_runtime.h>
#include <cuda_bf16.h>
#include <math.h>

// ---------------------------------------------------------------------------
// SimpleRetention (real-output build, all three GEMMs on mma.sync bf16 with
// hi/lo error-compensated split: hi*hi + hi*lo + lo*hi, fp32 accumulators).
// att uses a 2-stage cp.async pipeline (loads overlap tensor-core math).
// Decay window 128: gamma^128 ~ 1.4e-6 relative truncation (threshold 1e-3).
// ---------------------------------------------------------------------------

namespace {
constexpr int BATCH = 4;
constexpr int SEQ   = 2048;
constexpr int HD    = 256;
constexpr int K2W   = 2 * HD;             // 512
constexpr int WIN   = 128;
constexpr int NROW  = BATCH * SEQ;        // 8192
constexpr int NJ    = WIN / 64 + 1;       // 3
constexpr float LOG2_GAMMA = -0.15200309344504997f;

constexpr int PM = 128;                   // proj block M
constexpr int PN = 64;                    // proj block N
constexpr int KC = 32;                    // K chunk (proj + att)
constexpr int SSTR = KC + 8;              // smem stride = 40 elems (80 B)
constexpr int NCH = K2W / KC;             // 16 att K-chunks

constexpr int KC2 = 64;                   // out K chunk
constexpr int SST2 = KC2 + 8;             // out smem stride = 72
}

// scratch
__device__ float2        g_rot  [SEQ * HD];
__device__ __nv_bfloat16 g_QQh  [NROW * K2W];
__device__ __nv_bfloat16 g_QQl  [NROW * K2W];
__device__ __nv_bfloat16 g_KKh  [NROW * K2W];
__device__ __nv_bfloat16 g_KKl  [NROW * K2W];
__device__ float         g_Vm   [NROW * HD];
__device__ __nv_bfloat16 g_Vth  [HD * NROW];   // V^T split hi  [h][m]
__device__ __nv_bfloat16 g_Vtl  [HD * NROW];
__device__ __nv_bfloat16 g_bandh[NROW * WIN];  // decayed band, split hi
__device__ __nv_bfloat16 g_bandl[NROW * WIN];
__device__ __nv_bfloat16 g_Wh   [3 * HD * HD];
__device__ __nv_bfloat16 g_Wl   [3 * HD * HD];

__device__ __forceinline__ __nv_bfloat162 split_hi2(float a, float b,
                                                    __nv_bfloat162& lo)
{
    __nv_bfloat16 h0 = __float2bfloat16(a);
    __nv_bfloat16 h1 = __float2bfloat16(b);
    lo = __nv_bfloat162(__float2bfloat16(a - __bfloat162float(h0)),
                        __float2bfloat16(b - __bfloat162float(h1)));
    return __nv_bfloat162(h0, h1);
}

__device__ __forceinline__ void mma_bf16(
    float& d0, float& d1, float& d2, float& d3,
    unsigned a0, unsigned a1, unsigned a2, unsigned a3,
    unsigned b0, unsigned b1)
{
    asm volatile(
        "mma.sync.aligned.m16n8k16.row.col.f32.bf16.bf16.f32 "
        "{%0,%1,%2,%3}, {%4,%5,%6,%7}, {%8,%9}, {%0,%1,%2,%3};"
        : "+f"(d0), "+f"(d1), "+f"(d2), "+f"(d3)
        : "r"(a0), "r"(a1), "r"(a2), "r"(a3), "r"(b0), "r"(b1));
}

__device__ __forceinline__ void cp8(void* smem_dst, const void* gsrc)
{
    unsigned d = (unsigned)__cvta_generic_to_shared(smem_dst);
    asm volatile("cp.async.ca.shared.global [%0], [%1], 8;"
                 :: "r"(d), "l"(gsrc) : "memory");
}

// ---------------------------------------------------------------------------
// K0: rotation table
// ---------------------------------------------------------------------------
__global__ __launch_bounds__(256) void rot_kernel(const float* __restrict__ theta)
{
    int idx = blockIdx.x * 256 + threadIdx.x;
    int s = idx >> 8;
    int h = idx & (HD - 1);
    float ph = (float)(s + 1) * theta[h];
    float sn, cs;
    sincosf(ph, &sn, &cs);
    g_rot[idx] = make_float2(cs, sn);
}

// ---------------------------------------------------------------------------
// K0b: transpose + bf16-split weights:  g_W{h,l}[w][n][k] = W[w][k][n]
// ---------------------------------------------------------------------------
__global__ __launch_bounds__(256) void wconv_kernel(
    const float* __restrict__ W0, const float* __restrict__ W1,
    const float* __restrict__ W2)
{
    int o = blockIdx.x * 256 + threadIdx.x;
    int w = o >> 16;
    int n = (o >> 8) & 255;
    int k = o & 255;
    const float* W = (w == 0) ? W0 : (w == 1) ? W1 : W2;
    float x = W[k * HD + n];
    __nv_bfloat16 hi = __float2bfloat16(x);
    g_Wh[o] = hi;
    g_Wl[o] = __float2bfloat16(x - __bfloat162float(hi));
}

// ---------------------------------------------------------------------------
// K0c: V^T split:  g_Vt{h,l}[h][m] = split(g_Vm[m][h]).  Tiled transpose.
// ---------------------------------------------------------------------------
__global__ __launch_bounds__(256) void vtconv_kernel()
{
    __shared__ float t[32][33];
    const int mx = blockIdx.x * 32;
    const int hy = blockIdx.y * 32;
    const int tx = threadIdx.x, ty = threadIdx.y;

    #pragma unroll
    for (int j = 0; j < 4; j++)
        t[ty + j * 8][tx] = g_Vm[(mx + ty + j * 8) * HD + hy + tx];
    __syncthreads();

    #pragma unroll
    for (int j = 0; j < 4; j++) {
        int h = hy + ty + j * 8;
        float v = t[tx][ty + j * 8];
        __nv_bfloat16 hi = __float2bfloat16(v);
        g_Vth[(long long)h * NROW + mx + tx] = hi;
        g_Vtl[(long long)h * NROW + mx + tx] =
            __float2bfloat16(v - __bfloat162float(hi));
    }
}

// ---------------------------------------------------------------------------
// K1: proj via mma.sync.  grid (NROW/128, HD/64, 3), 256 threads.
// ---------------------------------------------------------------------------
__global__ __launch_bounds__(256) void proj_kernel(const float* __restrict__ X)
{
    __shared__ __align__(16) __nv_bfloat16 Ah[PM * SSTR];
    __shared__ __align__(16) __nv_bfloat16 Al[PM * SSTR];
    __shared__ __align__(16) __nv_bfloat16 Bh[PN * SSTR];
    __shared__ __align__(16) __nv_bfloat16 Bl[PN * SSTR];

    const int tid  = threadIdx.x;
    const int wid  = tid >> 5;
    const int lane = tid & 31;
    const int row0 = blockIdx.x * PM;
    const int col0 = blockIdx.y * PN;
    const int z    = blockIdx.z;

    const int wr0 = (wid & 3) * 32;
    const int wc0 = (wid >> 2) * 32;
    const int lr  = lane >> 2;
    const int lk  = (lane & 3) * 2;

    const __nv_bfloat16* Wh = g_Wh + z * HD * HD;
    const __nv_bfloat16* Wl = g_Wl + z * HD * HD;

    float acc[2][4][4] = {};

    for (int k0 = 0; k0 < HD; k0 += KC) {
        for (int i = tid; i < PM * (KC / 2); i += 256) {
            int r = i >> 4, kp = i & 15;
            float2 x2 = *(const float2*)&X[(row0 + r) * HD + k0 + kp * 2];
            __nv_bfloat162 lo2;
            __nv_bfloat162 hi2 = split_hi2(x2.x, x2.y, lo2);
            *(__nv_bfloat162*)&Ah[r * SSTR + kp * 2] = hi2;
            *(__nv_bfloat162*)&Al[r * SSTR + kp * 2] = lo2;
        }
        for (int i = tid; i < PN * (KC / 2); i += 256) {
            int n = i >> 4, kp = i & 15;
            unsigned gi = (unsigned)(col0 + n) * HD + k0 + kp * 2;
            *(unsigned*)&Bh[n * SSTR + kp * 2] = *(const unsigned*)&Wh[gi];
            *(unsigned*)&Bl[n * SSTR + kp * 2] = *(const unsigned*)&Wl[gi];
        }
        __syncthreads();

        #pragma unroll
        for (int ks = 0; ks < KC; ks += 16) {
            unsigned ah[2][4], al[2][4];
            #pragma unroll
            for (int mi = 0; mi < 2; mi++) {
                int r = wr0 + mi * 16 + lr;
                ah[mi][0] = *(const unsigned*)&Ah[r * SSTR + ks + lk];
                ah[mi][1] = *(const unsigned*)&Ah[(r + 8) * SSTR + ks + lk];
                ah[mi][2] = *(const unsigned*)&Ah[r * SSTR + ks + 8 + lk];
                ah[mi][3] = *(const unsigned*)&Ah[(r + 8) * SSTR + ks + 8 + lk];
                al[mi][0] = *(const unsigned*)&Al[r * SSTR + ks + lk];
                al[mi][1] = *(const unsigned*)&Al[(r + 8) * SSTR + ks + lk];
                al[mi][2] = *(const unsigned*)&Al[r * SSTR + ks + 8 + lk];
                al[mi][3] = *(const unsigned*)&Al[(r + 8) * SSTR + ks + 8 + lk];
            }
            unsigned bh[4][2], bl[4][2];
            #pragma unroll
            for (int nj = 0; nj < 4; nj++) {
                int n = wc0 + nj * 8 + lr;
                bh[nj][0] = *(const unsigned*)&Bh[n * SSTR + ks + lk];
                bh[nj][1] = *(const unsigned*)&Bh[n * SSTR + ks + 8 + lk];
                bl[nj][0] = *(const unsigned*)&Bl[n * SSTR + ks + lk];
                bl[nj][1] = *(const unsigned*)&Bl[n * SSTR + ks + 8 + lk];
            }
            #pragma unroll
            for (int mi = 0; mi < 2; mi++)
                #pragma unroll
                for (int nj = 0; nj < 4; nj++) {
                    float* d = acc[mi][nj];
                    mma_bf16(d[0], d[1], d[2], d[3],
                             ah[mi][0], ah[mi][1], ah[mi][2], ah[mi][3],
                             bh[nj][0], bh[nj][1]);
                    mma_bf16(d[0], d[1], d[2], d[3],
                             ah[mi][0], ah[mi][1], ah[mi][2], ah[mi][3],
                             bl[nj][0], bl[nj][1]);
                    mma_bf16(d[0], d[1], d[2], d[3],
                             al[mi][0], al[mi][1], al[mi][2], al[mi][3],
                             bh[nj][0], bh[nj][1]);
                }
        }
        __syncthreads();
    }

    #pragma unroll
    for (int mi = 0; mi < 2; mi++) {
        #pragma unroll
        for (int nj = 0; nj < 4; nj++) {
            int rloc = wr0 + mi * 16 + lr;
            int hloc = wc0 + nj * 8 + (lane & 3) * 2;
            #pragma unroll
            for (int half = 0; half < 2; half++) {
                int row = row0 + rloc + half * 8;
                float d0 = acc[mi][nj][half * 2];
                float d1 = acc[mi][nj][half * 2 + 1];
                int h = col0 + hloc;
                if (z == 2) {
                    g_Vm[row * HD + h]     = d0;
                    g_Vm[row * HD + h + 1] = d1;
                } else {
                    int s = row & (SEQ - 1);
                    float2 rt0 = g_rot[s * HD + h];
                    float2 rt1 = g_rot[s * HD + h + 1];
                    __nv_bfloat16* dh = (z == 0) ? g_QQh : g_KKh;
                    __nv_bfloat16* dl = (z == 0) ? g_QQl : g_KKl;
                    __nv_bfloat162 lo2;
                    __nv_bfloat162 hi2 = split_hi2(d0 * rt0.x, d1 * rt1.x, lo2);
                    *(__nv_bfloat162*)&dh[row * K2W + h] = hi2;
                    *(__nv_bfloat162*)&dl[row * K2W + h] = lo2;
                    hi2 = split_hi2(d0 * rt0.y, d1 * rt1.y, lo2);
                    *(__nv_bfloat162*)&dh[row * K2W + HD + h] = hi2;
                    *(__nv_bfloat162*)&dl[row * K2W + HD + h] = lo2;
                }
            }
        }
    }
}

// ---------------------------------------------------------------------------
// K2: att via mma.sync + 2-stage cp.async pipeline.
// grid (SEQ/64, NJ, BATCH), 256 threads.  smem 40 KB.
// ---------------------------------------------------------------------------
__global__ __launch_bounds__(256) void att_kernel()
{
    __shared__ __align__(16) __nv_bfloat16 Qh[2][64 * SSTR];
    __shared__ __align__(16) __nv_bfloat16 Ql[2][64 * SSTR];
    __shared__ __align__(16) __nv_bfloat16 Kh[2][64 * SSTR];
    __shared__ __align__(16) __nv_bfloat16 Kl[2][64 * SSTR];

    const int b  = blockIdx.z;
    const int n0 = blockIdx.x * 64;
    const int m0 = n0 - 64 * (int)blockIdx.y;
    if (m0 < 0) return;

    const int tid  = threadIdx.x;
    const int wid  = tid >> 5;
    const int lane = tid & 31;
    const int wr0  = (wid & 1) * 32;
    const int wc0  = (wid >> 1) * 16;
    const int lr   = lane >> 2;
    const int lk   = (lane & 3) * 2;
    const long long qbase = (long long)(b * SEQ + n0) * K2W;
    const long long kbase = (long long)(b * SEQ + m0) * K2W;

    // per-thread cp.async assignments: 2 x 8-byte chunks per array per stage
    const int i0 = tid * 2;

    auto issue = [&](int c, int st) {
        int k0 = c * KC;
        #pragma unroll
        for (int t = 0; t < 2; t++) {
            int i = i0 + t;                 // 0..511
            int r = i >> 3, ch = i & 7;     // row, 8B-chunk (4 bf16)
            long long g = (long long)r * K2W + k0 + ch * 4;
            int so = r * SSTR + ch * 4;
            cp8(&Qh[st][so], g_QQh + qbase + g);
            cp8(&Ql[st][so], g_QQl + qbase + g);
            cp8(&Kh[st][so], g_KKh + kbase + g);
            cp8(&Kl[st][so], g_KKl + kbase + g);
        }
        asm volatile("cp.async.commit_group;" ::: "memory");
    };

    float acc[2][2][4] = {};

    issue(0, 0);

    for (int c = 0; c < NCH; c++) {
        const int st = c & 1;
        asm volatile("cp.async.wait_group 0;" ::: "memory");
        __syncthreads();
        if (c + 1 < NCH) issue(c + 1, st ^ 1);

        #pragma unroll
        for (int ks = 0; ks < KC; ks += 16) {
            unsigned ah[2][4], al[2][4];
            #pragma unroll
            for (int mi = 0; mi < 2; mi++) {
                int r = wr0 + mi * 16 + lr;
                ah[mi][0] = *(const unsigned*)&Qh[st][r * SSTR + ks + lk];
                ah[mi][1] = *(const unsigned*)&Qh[st][(r + 8) * SSTR + ks + lk];
                ah[mi][2] = *(const unsigned*)&Qh[st][r * SSTR + ks + 8 + lk];
                ah[mi][3] = *(const unsigned*)&Qh[st][(r + 8) * SSTR + ks + 8 + lk];
                al[mi][0] = *(const unsigned*)&Ql[st][r * SSTR + ks + lk];
                al[mi][1] = *(const unsigned*)&Ql[st][(r + 8) * SSTR + ks + lk];
                al[mi][2] = *(const unsigned*)&Ql[st][r * SSTR + ks + 8 + lk];
                al[mi][3] = *(const unsigned*)&Ql[st][(r + 8) * SSTR + ks + 8 + lk];
            }
            unsigned bh[2][2], bl[2][2];
            #pragma unroll
            for (int nj = 0; nj < 2; nj++) {
                int n = wc0 + nj * 8 + lr;
                bh[nj][0] = *(const unsigned*)&Kh[st][n * SSTR + ks + lk];
                bh[nj][1] = *(const unsigned*)&Kh[st][n * SSTR + ks + 8 + lk];
                bl[nj][0] = *(const unsigned*)&Kl[st][n * SSTR + ks + lk];
                bl[nj][1] = *(const unsigned*)&Kl[st][n * SSTR + ks + 8 + lk];
            }
            #pragma unroll
            for (int mi = 0; mi < 2; mi++)
                #pragma unroll
                for (int nj = 0; nj < 2; nj++) {
                    float* d = acc[mi][nj];
                    mma_bf16(d[0], d[1], d[2], d[3],
                             ah[mi][0], ah[mi][1], ah[mi][2], ah[mi][3],
                             bh[nj][0], bh[nj][1]);
                    mma_bf16(d[0], d[1], d[2], d[3],
                             ah[mi][0], ah[mi][1], ah[mi][2], ah[mi][3],
                             bl[nj][0], bl[nj][1]);
                    mma_bf16(d[0], d[1], d[2], d[3],
                             al[mi][0], al[mi][1], al[mi][2], al[mi][3],
                             bh[nj][0], bh[nj][1]);
                }
        }
        __syncthreads();
    }

    // epilogue: decay + split bf16 banded store
    #pragma unroll
    for (int mi = 0; mi < 2; mi++) {
        #pragma unroll
        for (int nj = 0; nj < 2; nj++) {
            #pragma unroll
            for (int half = 0; half < 2; half++) {
                int n = n0 + wr0 + mi * 16 + lr + half * 8;
                int m = m0 + wc0 + nj * 8 + (lane & 3) * 2;
                float d0 = acc[mi][nj][half * 2];
                float d1 = acc[mi][nj][half * 2 + 1];
                int dd0 = n - m, dd1 = n - m - 1;
                if (dd0 >= 0 && dd0 < WIN) {
                    float v = d0 * exp2f((float)dd0 * LOG2_GAMMA);
                    __nv_bfloat16 hi = __float2bfloat16(v);
                    long long ix = (long long)(b * SEQ + n) * WIN + dd0;
                    g_bandh[ix] = hi;
                    g_bandl[ix] = __float2bfloat16(v - __bfloat162float(hi));
                }
                if (dd1 >= 0 && dd1 < WIN) {
                    float v = d1 * exp2f((float)dd1 * LOG2_GAMMA);
                    __nv_bfloat16 hi = __float2bfloat16(v);
                    long long ix = (long long)(b * SEQ + n) * WIN + dd1;
                    g_bandh[ix] = hi;
                    g_bandl[ix] = __float2bfloat16(v - __bfloat162float(hi));
                }
            }
        }
    }
}

// ---------------------------------------------------------------------------
// K3: out via mma.sync.  D[n][h] = sum_m band[n][m] * Vt[h][m].
// grid (SEQ/64, HD/64, BATCH), 256 threads, 3 m-tiles of K=64 each.
// ---------------------------------------------------------------------------
__global__ __launch_bounds__(256) void out_kernel(float* __restrict__ out,
                                                  long long out_elems)
{
    __shared__ __align__(16) __nv_bfloat16 Ah[64 * SST2];
    __shared__ __align__(16) __nv_bfloat16 Al[64 * SST2];
    __shared__ __align__(16) __nv_bfloat16 Vh[64 * SST2];
    __shared__ __align__(16) __nv_bfloat16 Vl[64 * SST2];

    const int b  = blockIdx.z;
    const int n0 = blockIdx.x * 64;
    const int h0 = blockIdx.y * 64;
    const int tid  = threadIdx.x;
    const int wid  = tid >> 5;
    const int lane = tid & 31;
    const int wr0  = (wid & 1) * 32;
    const int wc0  = (wid >> 1) * 16;
    const int lr   = lane >> 2;
    const int lk   = (lane & 3) * 2;

    float acc[2][2][4] = {};

    for (int jt = 0; jt < NJ; jt++) {
        int m0 = n0 - 64 * jt;
        if (m0 < 0) break;

        for (int i = tid; i < 64 * 64; i += 256) {
            int nl = i >> 6, ml = i & 63;
            int d = 64 * jt + nl - ml;
            __nv_bfloat16 hi(0.f), lo(0.f);
            if (d >= 0 && d < WIN) {
                long long ix = (long long)(b * SEQ + n0 + nl) * WIN + d;
                hi = g_bandh[ix];
                lo = g_bandl[ix];
            }
            Ah[nl * SST2 + ml] = hi;
            Al[nl * SST2 + ml] = lo;
        }
        for (int i = tid; i < 64 * (KC2 / 2); i += 256) {
            int r = i >> 5, kp = i & 31;
            long long gi = (long long)(h0 + r) * NROW + b * SEQ + m0 + kp * 2;
            *(unsigned*)&Vh[r * SST2 + kp * 2] = *(const unsigned*)&g_Vth[gi];
            *(unsigned*)&Vl[r * SST2 + kp * 2] = *(const unsigned*)&g_Vtl[gi];
        }
        __syncthreads();

        #pragma unroll
        for (int ks = 0; ks < KC2; ks += 16) {
            unsigned ah[2][4], al[2][4];
            #pragma unroll
            for (int mi = 0; mi < 2; mi++) {
                int r = wr0 + mi * 16 + lr;
                ah[mi][0] = *(const unsigned*)&Ah[r * SST2 + ks + lk];
                ah[mi][1] = *(const unsigned*)&Ah[(r + 8) * SST2 + ks + lk];
                ah[mi][2] = *(const unsigned*)&Ah[r * SST2 + ks + 8 + lk];
                ah[mi][3] = *(const unsigned*)&Ah[(r + 8) * SST2 + ks + 8 + lk];
                al[mi][0] = *(const unsigned*)&Al[r * SST2 + ks + lk];
                al[mi][1] = *(const unsigned*)&Al[(r + 8) * SST2 + ks + lk];
                al[mi][2] = *(const unsigned*)&Al[r * SST2 + ks + 8 + lk];
                al[mi][3] = *(const unsigned*)&Al[(r + 8) * SST2 + ks + 8 + lk];
            }
            unsigned bh[2][2], bl[2][2];
            #pragma unroll
            for (int nj = 0; nj < 2; nj++) {
                int n = wc0 + nj * 8 + lr;
                bh[nj][0] = *(const unsigned*)&Vh[n * SST2 + ks + lk];
                bh[nj][1] = *(const unsigned*)&Vh[n * SST2 + ks + 8 + lk];
                bl[nj][0] = *(const unsigned*)&Vl[n * SST2 + ks + lk];
                bl[nj][1] = *(const unsigned*)&Vl[n * SST2 + ks + 8 + lk];
            }
            #pragma unroll
            for (int mi = 0; mi < 2; mi++)
                #pragma unroll
                for (int nj = 0; nj < 2; nj++) {
                    float* d = acc[mi][nj];
                    mma_bf16(d[0], d[1], d[2], d[3],
                             ah[mi][0], ah[mi][1], ah[mi][2], ah[mi][3],
                             bh[nj][0], bh[nj][1]);
                    mma_bf16(d[0], d[1], d[2], d[3],
                             ah[mi][0], ah[mi][1], ah[mi][2], ah[mi][3],
                             bl[nj][0], bl[nj][1]);
                    mma_bf16(d[0], d[1], d[2], d[3],
                             al[mi][0], al[mi][1], al[mi][2], al[mi][3],
                             bh[nj][0], bh[nj][1]);
                }
        }
        __syncthreads();
    }

    #pragma unroll
    for (int mi = 0; mi < 2; mi++) {
        #pragma unroll
        for (int nj = 0; nj < 2; nj++) {
            #pragma unroll
            for (int half = 0; half < 2; half++) {
                int n = n0 + wr0 + mi * 16 + lr + half * 8;
                int h = h0 + wc0 + nj * 8 + (lane & 3) * 2;
                long long idx = ((long long)b * SEQ + n) * HD + h;
                if (idx + 1 < out_elems) {
                    out[idx]     = acc[mi][nj][half * 2];
                    out[idx + 1] = acc[mi][nj][half * 2 + 1];
                }
            }
        }
    }
}

// ---------------------------------------------------------------------------
// launch
// ---------------------------------------------------------------------------
extern "C" void kernel_launch(void* const* d_in, const int* in_sizes, int n_in,
                              void* d_out, int out_size)
{
    constexpr int XN = BATCH * SEQ * HD;
    constexpr int WN = HD * HD;
    constexpr int TN = HD;

    const float* X = nullptr;
    const float* theta = nullptr;
    const float* W[3] = {nullptr, nullptr, nullptr};
    int wn = 0;

    for (int i = 0; i < n_in; i++) {
        int s = in_sizes[i];
        if (s == XN)                X = (const float*)d_in[i];
        else if (s == TN)           theta = (const float*)d_in[i];
        else if (s == WN && wn < 3) W[wn++] = (const float*)d_in[i];
    }
    if (!X || !theta || wn < 3) return;

    float* out = (float*)d_out;

    rot_kernel<<<SEQ * HD / 256, 256>>>(theta);
    wconv_kernel<<<3 * HD * HD / 256, 256>>>(W[0], W[1], W[2]);
    proj_kernel<<<dim3(NROW / PM, HD / PN, 3), 256>>>(X);
    vtconv_kernel<<<dim3(NROW / 32, HD / 32), dim3(32, 8)>>>();
    att_kernel<<<dim3(SEQ / 64, NJ, BATCH), 256>>>();
    out_kernel<<<dim3(SEQ / 64, HD / 64, BATCH), 256>>>(out, (long long)out_size);
}